// round 2
// baseline (speedup 1.0000x reference)
#include <cuda_runtime.h>
#include <cuda_bf16.h>
#include <math.h>

// Problem constants
#define BB 4
#define SS 1024
#define EE 1024
#define HH 16
#define DH 64
#define ROWS (BB*SS)           // 4096
#define LN_EPS 1e-5f

// ---------------- scratch (device globals; no allocation allowed) ----------------
__device__ float g_h   [ROWS*EE];                 // 16MB  ln1 out
__device__ float g_qkv [ROWS*3*EE];               // 48MB  qkv
__device__ float g_probs[(long long)BB*HH*SS*SS]; // 256MB probs
__device__ float g_att [ROWS*EE];                 // 16MB  attention out (B,S,H,DH)
__device__ float g_x1  [ROWS*EE];                 // 16MB  x + attproj
__device__ float g_h2  [ROWS*EE];                 // 16MB  ln2 out
__device__ float g_fc  [ROWS*4*EE];               // 64MB  gelu(fc)

// ---------------- LayerNorm: one block per row ----------------
__global__ void ln_kernel(const float* __restrict__ x,
                          const float* __restrict__ g,
                          const float* __restrict__ b,
                          float* __restrict__ out)
{
    long long row = blockIdx.x;
    const float* xr = x + row * EE;
    float* orow = out + row * EE;
    __shared__ float red[256];
    int tid = threadIdx.x;

    float s = 0.f;
    #pragma unroll
    for (int c = tid; c < EE; c += 256) s += xr[c];
    red[tid] = s; __syncthreads();
    for (int st = 128; st > 0; st >>= 1) { if (tid < st) red[tid] += red[tid+st]; __syncthreads(); }
    float mu = red[0] * (1.f/EE);
    __syncthreads();

    float v = 0.f;
    #pragma unroll
    for (int c = tid; c < EE; c += 256) { float d = xr[c] - mu; v += d*d; }
    red[tid] = v; __syncthreads();
    for (int st = 128; st > 0; st >>= 1) { if (tid < st) red[tid] += red[tid+st]; __syncthreads(); }
    float inv = rsqrtf(red[0] * (1.f/EE) + LN_EPS);
    __syncthreads();

    #pragma unroll
    for (int c = tid; c < EE; c += 256)
        orow[c] = (xr[c] - mu) * inv * g[c] + b[c];
}

// ---------------- generic tiled GEMM ----------------
// C[m,n] = alpha * sum_k A[m,k] * B(k,n)  (+bias[n]) (+resid[m,n]) (gelu) (causal mask)
// TRANSB=true : B stored [N,K] row-major -> B[n*ldb + k]
// TRANSB=false: B stored [K,N] row-major -> B[k*ldb + n]
// Batched via blockIdx.z = bb*Hdiv + hh with separate b/h strides.
// All dims must be multiples of the tile (true for every call here).
template<bool TRANSB>
__global__ __launch_bounds__(256)
void gemm_kernel(const float* __restrict__ Abase,
                 const float* __restrict__ Bbase,
                 float* __restrict__ Cbase,
                 const float* __restrict__ bias,
                 const float* __restrict__ resid,
                 int M, int N, int K,
                 int lda, int ldb, int ldc,
                 long long sAb, long long sAh,
                 long long sBb, long long sBh,
                 long long sCb, long long sCh,
                 int Hdiv, float alpha, int doGelu, int doMask)
{
    int z  = blockIdx.z;
    int bb = z / Hdiv, hh = z % Hdiv;
    const float* A  = Abase + (long long)bb*sAb + (long long)hh*sAh;
    const float* Bp = Bbase + (long long)bb*sBb + (long long)hh*sBh;
    float*       C  = Cbase + (long long)bb*sCb + (long long)hh*sCh;

    __shared__ float As[16][68];   // row stride 272B = 17*16B -> float4-aligned
    __shared__ float Bs[16][68];

    int tid = threadIdx.x;            // 256 threads
    int tx = tid & 15, ty = tid >> 4; // 16x16
    int m0 = blockIdx.y * 64, n0 = blockIdx.x * 64;

    float acc[4][4] = {};

    for (int k0 = 0; k0 < K; k0 += 16) {
        // A tile: 64 x 16 -> As[k][m]
        {
            int k = tid & 15, m = tid >> 4;
            #pragma unroll
            for (int r = 0; r < 4; r++) {
                int mm = m + r*16;
                As[k][mm] = A[(long long)(m0+mm)*lda + k0 + k];
            }
        }
        // B tile: 16 x 64 -> Bs[k][n]
        if (TRANSB) {
            int k = tid & 15, n = tid >> 4;
            #pragma unroll
            for (int r = 0; r < 4; r++) {
                int nn = n + r*16;
                Bs[k][nn] = Bp[(long long)(n0+nn)*ldb + k0 + k];
            }
        } else {
            int n = tid & 63, k = tid >> 6;
            #pragma unroll
            for (int r = 0; r < 4; r++) {
                int kk = k + r*4;
                Bs[kk][n] = Bp[(long long)(k0+kk)*ldb + n0 + n];
            }
        }
        __syncthreads();

        #pragma unroll
        for (int kk = 0; kk < 16; kk++) {
            float4 a4 = *reinterpret_cast<const float4*>(&As[kk][ty*4]);
            float4 b4 = *reinterpret_cast<const float4*>(&Bs[kk][tx*4]);
            float a[4] = {a4.x, a4.y, a4.z, a4.w};
            float bv[4] = {b4.x, b4.y, b4.z, b4.w};
            #pragma unroll
            for (int i = 0; i < 4; i++)
                #pragma unroll
                for (int j = 0; j < 4; j++)
                    acc[i][j] = fmaf(a[i], bv[j], acc[i][j]);
        }
        __syncthreads();
    }

    #pragma unroll
    for (int i = 0; i < 4; i++) {
        int m = m0 + ty*4 + i;
        #pragma unroll
        for (int j = 0; j < 4; j++) {
            int n = n0 + tx*4 + j;
            float c = acc[i][j] * alpha;
            if (bias)  c += bias[n];
            if (resid) c += resid[(long long)m*ldc + n];
            if (doGelu) {
                float xg = c;
                float t = tanhf(0.7978845608028654f * (xg + 0.044715f*xg*xg*xg));
                c = 0.5f * xg * (1.f + t);
            }
            if (doMask && n > m) c = -1e30f;   // causal: k > q
            C[(long long)m*ldc + n] = c;
        }
    }
}

// ---------------- softmax over last dim (1024), one block per row ----------------
__global__ void softmax_kernel(float* __restrict__ p)
{
    long long row = blockIdx.x;
    float* r = p + row * (long long)SS;
    __shared__ float red[256];
    int tid = threadIdx.x;

    float mx = -1e30f;
    #pragma unroll
    for (int c = tid; c < SS; c += 256) mx = fmaxf(mx, r[c]);
    red[tid] = mx; __syncthreads();
    for (int st = 128; st > 0; st >>= 1) { if (tid < st) red[tid] = fmaxf(red[tid], red[tid+st]); __syncthreads(); }
    mx = red[0]; __syncthreads();

    float sum = 0.f;
    #pragma unroll
    for (int c = tid; c < SS; c += 256) { float e = __expf(r[c] - mx); r[c] = e; sum += e; }
    red[tid] = sum; __syncthreads();
    for (int st = 128; st > 0; st >>= 1) { if (tid < st) red[tid] += red[tid+st]; __syncthreads(); }
    float inv = 1.f / red[0];
    __syncthreads();

    #pragma unroll
    for (int c = tid; c < SS; c += 256) r[c] *= inv;
}

// ---------------- att_weights = mean over heads of probs ----------------
__global__ void attw_kernel(const float* __restrict__ probs, float* __restrict__ out)
{
    long long idx = (long long)blockIdx.x * 256 + threadIdx.x;
    if (idx >= (long long)BB*SS*SS) return;
    long long b   = idx / ((long long)SS*SS);
    long long rem = idx % ((long long)SS*SS);
    float s = 0.f;
    #pragma unroll
    for (int h = 0; h < HH; h++)
        s += probs[(b*HH + h) * (long long)SS*SS + rem];
    out[idx] = s * (1.f/HH);
}

// ---------------- launch ----------------
extern "C" void kernel_launch(void* const* d_in, const int* in_sizes, int n_in,
                              void* d_out, int out_size)
{
    const float* x      = (const float*)d_in[0];
    // d_in[1] = causal_mask (tril logic applied directly in scores epilogue)
    const float* ln1_g  = (const float*)d_in[2];
    const float* ln1_b  = (const float*)d_in[3];
    const float* ln2_g  = (const float*)d_in[4];
    const float* ln2_b  = (const float*)d_in[5];
    const float* w_in   = (const float*)d_in[6];
    const float* b_in   = (const float*)d_in[7];
    const float* w_out  = (const float*)d_in[8];
    const float* b_out  = (const float*)d_in[9];
    const float* w_fc   = (const float*)d_in[10];
    const float* b_fc   = (const float*)d_in[11];
    const float* w_proj = (const float*)d_in[12];
    const float* b_proj = (const float*)d_in[13];

    float* out_x = (float*)d_out;                       // 4M floats
    float* out_w = (float*)d_out + (long long)ROWS*EE;  // 4M floats (att_weights)

    float *h, *qkv, *probs, *att, *x1, *h2, *fc;
    cudaGetSymbolAddress((void**)&h,     g_h);
    cudaGetSymbolAddress((void**)&qkv,   g_qkv);
    cudaGetSymbolAddress((void**)&probs, g_probs);
    cudaGetSymbolAddress((void**)&att,   g_att);
    cudaGetSymbolAddress((void**)&x1,    g_x1);
    cudaGetSymbolAddress((void**)&h2,    g_h2);
    cudaGetSymbolAddress((void**)&fc,    g_fc);

    const long long SSS = (long long)SS*SS;

    // 1) LN1
    ln_kernel<<<ROWS, 256>>>(x, ln1_g, ln1_b, h);

    // 2) QKV: [4096,3072] = h[4096,1024] @ w_in[3072,1024]^T + b_in
    gemm_kernel<true><<<dim3(3*EE/64, ROWS/64, 1), 256>>>(
        h, w_in, qkv, b_in, nullptr,
        ROWS, 3*EE, EE, EE, EE, 3*EE,
        0,0, 0,0, 0,0, 1, 1.f, 0, 0);

    // 3) scores: per (b,h): probs = scale * q @ k^T (+causal)  (M=N=1024, K=64)
    gemm_kernel<true><<<dim3(SS/64, SS/64, BB*HH), 256>>>(
        qkv /*q*/, qkv + EE /*k*/, probs, nullptr, nullptr,
        SS, SS, DH, 3*EE, 3*EE, SS,
        (long long)SS*3*EE, DH,
        (long long)SS*3*EE, DH,
        (long long)HH*SSS, SSS,
        HH, 0.125f, 0, 1);

    // 4) softmax rows = B*H*S
    softmax_kernel<<<BB*HH*SS, 256>>>(probs);

    // 5) att_weights = mean over heads
    attw_kernel<<<(int)((BB*SSS + 255)/256), 256>>>(probs, out_w);

    // 6) att[b,q,h,d] = probs[b,h] @ v[b,:,h,:]   (M=1024, N=64, K=1024)
    gemm_kernel<false><<<dim3(DH/64, SS/64, BB*HH), 256>>>(
        probs, qkv + 2*EE /*v*/, att, nullptr, nullptr,
        SS, DH, SS, SS, 3*EE, EE,
        (long long)HH*SSS, SSS,
        (long long)SS*3*EE, DH,
        (long long)SS*EE, DH,
        HH, 1.f, 0, 0);

    // 7) x1 = x + att @ w_out^T + b_out
    gemm_kernel<true><<<dim3(EE/64, ROWS/64, 1), 256>>>(
        att, w_out, x1, b_out, x,
        ROWS, EE, EE, EE, EE, EE,
        0,0, 0,0, 0,0, 1, 1.f, 0, 0);

    // 8) LN2
    ln_kernel<<<ROWS, 256>>>(x1, ln2_g, ln2_b, h2);

    // 9) fc = gelu(h2 @ w_fc^T + b_fc)   [4096,4096]
    gemm_kernel<true><<<dim3(4*EE/64, ROWS/64, 1), 256>>>(
        h2, w_fc, fc, b_fc, nullptr,
        ROWS, 4*EE, EE, EE, EE, 4*EE,
        0,0, 0,0, 0,0, 1, 1.f, 1, 0);

    // 10) out_x = x1 + fc @ w_proj^T + b_proj   [4096,1024]
    gemm_kernel<true><<<dim3(EE/64, ROWS/64, 1), 256>>>(
        fc, w_proj, out_x, b_proj, x1,
        ROWS, EE, 4*EE, 4*EE, 4*EE, EE,
        0,0, 0,0, 0,0, 1, 1.f, 0, 0);
}